// round 6
// baseline (speedup 1.0000x reference)
#include <cuda_runtime.h>
#include <cuda_fp16.h>
#include <cstdint>

// ---------------------------------------------------------------------------
// IWHT3Layer, round 6: fp16 mma.sync + cp.async f32 x-ring (depth 4).
//   CTA 32 pixels x 64 k, 512 threads / 16 warps (warp tile m16 x n8, all 16 t
//   accumulated in regs), in-register 2D WHT epilogue, per-lane float2 stores.
//   x path: cp.async.cg 16B/thread -> 4-slot f32 ring (self-read, no extra
//   syncs) -> cvt fp16 -> STS -> ldmatrix. ~3 iters of load slack.
//   B path: pre-fragmented fp16 per-lane, 32B/warp/t contiguous (2x LDG.128),
//   register double-buffered, L2-hot.
// ---------------------------------------------------------------------------

#define U32 unsigned int
#define U64 unsigned long long

static constexpr int PIXELS   = 12544;
static constexpr int PIX_CTA  = 32;
static constexpr int NBLK     = PIXELS / PIX_CTA;   // 392
static constexpr int T_STRIDE = PIXELS * 64;
static constexpr long long OPB = 16LL * 112 * 112 * 64;

static constexpr int A_PITCH  = 144;                 // conflict-free ldmatrix+STS
static constexpr int A_BUF    = 32 * A_PITCH;        // 4608 B per f16 buffer
static constexpr int XR_OFF   = 2 * A_BUF;           // 9216, 16B aligned
static constexpr int XSLOT    = 32 * 256;            // 8192 B per f32 slot
static constexpr int SMEM_SZ  = XR_OFF + 4 * XSLOT;  // 41984 B (static)

// B fragments: per (branch,t,nb,lane): 4 x U64 (kc 0..3) contiguous (32B)
__device__ __align__(16) U64 g_bfrag[3 * 16 * 8 * 32 * 4];

// ---------------- helpers ----------------
__device__ __forceinline__ U32 smem_u32(const void* p) {
    U32 a; asm("{ .reg .u64 t; cvta.to.shared.u64 t, %1; cvt.u32.u64 %0, t; }"
               : "=r"(a) : "l"(p)); return a;
}
__device__ __forceinline__ void ldm4(U32& a0, U32& a1, U32& a2, U32& a3, U32 addr) {
    asm volatile("ldmatrix.sync.aligned.m8n8.x4.shared.b16 {%0,%1,%2,%3}, [%4];"
                 : "=r"(a0), "=r"(a1), "=r"(a2), "=r"(a3) : "r"(addr));
}
__device__ __forceinline__ void mma16816(float* d, U32 a0, U32 a1, U32 a2, U32 a3,
                                         U32 b0, U32 b1) {
    asm volatile("mma.sync.aligned.m16n8k16.row.col.f32.f16.f16.f32 "
                 "{%0,%1,%2,%3}, {%4,%5,%6,%7}, {%8,%9}, {%0,%1,%2,%3};"
                 : "+f"(d[0]), "+f"(d[1]), "+f"(d[2]), "+f"(d[3])
                 : "r"(a0), "r"(a1), "r"(a2), "r"(a3), "r"(b0), "r"(b1));
}
__device__ __forceinline__ void cpa16(U32 dst_smem, const void* src) {
    asm volatile("cp.async.cg.shared.global [%0], [%1], 16;" :: "r"(dst_smem), "l"(src));
}
#define CP_COMMIT() asm volatile("cp.async.commit_group;")
#define CP_WAIT2()  asm volatile("cp.async.wait_group 2;")

struct F2 { float x, y; };
__device__ __forceinline__ F2 f2add(F2 a, F2 b) { return {a.x + b.x, a.y + b.y}; }
__device__ __forceinline__ F2 f2sub(F2 a, F2 b) { return {a.x - b.x, a.y - b.y}; }

// ---------------- prep: build fp16 B fragments (one-time) ----------------
__global__ void wprep_kernel(const float* __restrict__ w1,
                             const float* __restrict__ w2,
                             const float* __restrict__ w3) {
    int br = blockIdx.x >> 4, t = blockIdx.x & 15;
    const float* w = (br == 0 ? w1 : (br == 1 ? w2 : w3)) + t * 4096;
    __half* frag = (__half*)g_bfrag;
    for (int idx = threadIdx.x; idx < 4096; idx += blockDim.x) {
        int c = idx >> 6, k = idx & 63;          // w[c][k], coalesced over k
        __half h = __float2half(w[idx]);
        int kc = c >> 4, cw = c & 15;
        int nb = k >> 3, lane = (k & 7) * 4 + ((cw & 7) >> 1);
        int regj = cw >> 3, half = cw & 1;
        size_t u64i = ((((size_t)(br * 16 + t) * 8 + nb) * 32 + lane) * 4 + kc);
        frag[u64i * 4 + regj * 2 + half] = h;
    }
}

// ---------------- main kernel ----------------
__global__ __launch_bounds__(512, 1)
void iwht_mma_kernel(const float* __restrict__ tr1, const float* __restrict__ tr2,
                     const float* __restrict__ tr3,
                     const float* __restrict__ b1, const float* __restrict__ b2,
                     const float* __restrict__ b3,
                     float* __restrict__ out) {
    __shared__ __align__(16) char smem[SMEM_SZ];

    const int tid  = threadIdx.x;
    const int lane = tid & 31;
    const int w    = tid >> 5;     // 0..15
    const int mb   = w & 1;        // m16 block (pixels)
    const int nb   = w >> 1;       // n8 block (k outputs)

    const int branch = blockIdx.y;
    const float* tr   = (branch == 0 ? tr1 : (branch == 1 ? tr2 : tr3));
    const float* bias = (branch == 0 ? b1  : (branch == 1 ? b2  : b3));
    const int pix0 = blockIdx.x * PIX_CTA;

    // conversion role: thread -> (row 0..31, 4 floats at cseg*4)
    const int crow = tid >> 4, cseg = tid & 15;
    const float* xrow = tr + (size_t)(pix0 + crow) * 64 + cseg * 4;
    const U32 sbase = smem_u32(smem);
    const U32 xslot_my = sbase + (U32)(XR_OFF + crow * 256 + cseg * 16);

    auto cvtStore = [&](float4 a, int buf) {
        __half2 h0 = __floats2half2_rn(a.x, a.y);
        __half2 h1 = __floats2half2_rn(a.z, a.w);
        *(uint2*)(smem + buf * A_BUF + crow * A_PITCH + cseg * 8) =
            make_uint2(*reinterpret_cast<U32*>(&h0), *reinterpret_cast<U32*>(&h1));
    };

    // B fragments: 32B contiguous per (t, warp, lane)
    const U64* gb = g_bfrag +
        (((size_t)branch * 16 * 8 + nb) * 32 + lane) * 4;
    auto loadB = [&](int t, U64* dst) {
        const uint4* p = (const uint4*)(gb + (size_t)t * 8 * 32 * 4);
        uint4 v0 = p[0], v1 = p[1];
        dst[0] = (U64)v0.x | ((U64)v0.y << 32);
        dst[1] = (U64)v0.z | ((U64)v0.w << 32);
        dst[2] = (U64)v1.x | ((U64)v1.y << 32);
        dst[3] = (U64)v1.z | ((U64)v1.w << 32);
    };

    // ---------------- prologue ----------------
    cvtStore(*(const float4*)xrow, 0);                 // t=0 synchronous
    #pragma unroll
    for (int t = 1; t <= 3; t++) {                     // groups 1..3 in flight
        cpa16(xslot_my + (t & 3) * XSLOT, xrow + (size_t)t * T_STRIDE);
        CP_COMMIT();
    }
    U64 bcur[4], bnxt[4];
    loadB(0, bcur);
    __syncthreads();

    const U32 arow0 = sbase + (U32)((mb * 16 + (lane & 15)) * A_PITCH + (lane >> 4) * 16);

    float acc[16][4];
    #pragma unroll
    for (int t = 0; t < 16; t++)
        #pragma unroll
        for (int i = 0; i < 4; i++) acc[t][i] = 0.0f;

    #pragma unroll
    for (int t = 0; t < 16; t++) {
        // MMAs for t (A staged last iter in f16buf[t&1])
        const U32 ab = arow0 + (U32)((t & 1) * A_BUF);
        #pragma unroll
        for (int kc = 0; kc < 4; kc++) {
            U32 a0, a1, a2, a3;
            ldm4(a0, a1, a2, a3, ab + kc * 32);
            mma16816(acc[t], a0, a1, a2, a3,
                     (U32)bcur[kc], (U32)(bcur[kc] >> 32));
        }

        if (t < 15) {
            loadB(t + 1, bnxt);                        // L2-hot, 2x LDG.128
            CP_WAIT2();                                // group (t+1) complete
            float4 v = *(const float4*)(smem + XR_OFF + ((t + 1) & 3) * XSLOT
                                        + crow * 256 + cseg * 16);
            cvtStore(v, (t + 1) & 1);
            if (t + 4 <= 15)
                cpa16(xslot_my + ((t + 4) & 3) * XSLOT,
                      xrow + (size_t)(t + 4) * T_STRIDE);
            CP_COMMIT();                               // (possibly empty) group
            #pragma unroll
            for (int kc = 0; kc < 4; kc++) bcur[kc] = bnxt[kc];
        }
        __syncthreads();
    }

    // ---------------- epilogue: in-register 2D WHT + bias + stores ----------
    const int cl = lane & 3, rl = lane >> 2;
    float* outB = out + (size_t)branch * OPB;
    const int kst = nb * 8 + cl * 2;
    const float2 bv = *(const float2*)(bias + kst);

    #pragma unroll
    for (int rh = 0; rh < 2; rh++) {
        const int P = pix0 + mb * 16 + rh * 8 + rl;
        const int pb_ = P / 784, rr = P - pb_ * 784;
        const int ii = rr / 28, jj = rr - ii * 28;
        float* obase = outB + ((size_t)(pb_ * 112 + ii * 4) * 112 + jj * 4) * 64 + kst;

        // u-stage butterflies over t = 4u+v
        F2 U[4][4];
        #pragma unroll
        for (int v = 0; v < 4; v++) {
            F2 y0 = {acc[v][rh * 2],      acc[v][rh * 2 + 1]};
            F2 y1 = {acc[4 + v][rh * 2],  acc[4 + v][rh * 2 + 1]};
            F2 y2 = {acc[8 + v][rh * 2],  acc[8 + v][rh * 2 + 1]};
            F2 y3 = {acc[12 + v][rh * 2], acc[12 + v][rh * 2 + 1]};
            F2 s0 = f2add(y0, y2), s1 = f2add(y1, y3);
            F2 d0 = f2sub(y0, y2), d1 = f2sub(y1, y3);
            U[0][v] = f2add(s0, s1); U[1][v] = f2sub(s0, s1);
            U[2][v] = f2add(d0, d1); U[3][v] = f2sub(d0, d1);
        }
        #pragma unroll
        for (int p = 0; p < 4; p++) {
            F2 s0 = f2add(U[p][0], U[p][2]), s1 = f2add(U[p][1], U[p][3]);
            F2 d0 = f2sub(U[p][0], U[p][2]), d1 = f2sub(U[p][1], U[p][3]);
            F2 Z[4];
            Z[0] = f2add(s0, s1); Z[1] = f2sub(s0, s1);
            Z[2] = f2add(d0, d1); Z[3] = f2sub(d0, d1);
            float* orow = obase + (size_t)p * 7168;      // 112*64
            #pragma unroll
            for (int q = 0; q < 4; q++) {
                float zx = fmaf(Z[q].x, 0.0625f, bv.x);
                float zy = fmaf(Z[q].y, 0.0625f, bv.y);
                *(float2*)(orow + q * 64) = make_float2(zx, zy);
            }
        }
    }
}

// ---------------- launch ----------------
extern "C" void kernel_launch(void* const* d_in, const int* in_sizes, int n_in,
                              void* d_out, int out_size) {
    (void)in_sizes; (void)n_in; (void)out_size;
    const float* tr1 = (const float*)d_in[0];
    const float* tr2 = (const float*)d_in[1];
    const float* tr3 = (const float*)d_in[2];
    const float* w1  = (const float*)d_in[3];
    const float* w2  = (const float*)d_in[4];
    const float* w3  = (const float*)d_in[5];
    const float* b1  = (const float*)d_in[6];
    const float* b2  = (const float*)d_in[7];
    const float* b3  = (const float*)d_in[8];
    float* out = (float*)d_out;

    wprep_kernel<<<48, 256>>>(w1, w2, w3);
    dim3 grid(NBLK, 3);
    iwht_mma_kernel<<<grid, 512>>>(tr1, tr2, tr3, b1, b2, b3, out);
}